// round 15
// baseline (speedup 1.0000x reference)
#include <cuda_runtime.h>
#include <cuda_fp16.h>
#include <math.h>
#include <stdint.h>

#define BATCH 4
#define SEQ   2048
#define DIM   1024
#define MROWS (BATCH * SEQ)

// Scratch (__device__ globals). GEMM inputs in fp16 (rounded at producer).
__device__ __half g_xh[MROWS * DIM];
__device__ __half g_qh[BATCH * SEQ * DIM];
__device__ __half g_kh[BATCH * SEQ * DIM];
__device__ __half g_vth[BATCH * DIM * SEQ];          // V^T [dim][seq]
__device__ __half g_wth[3 * DIM * DIM];              // W^T [n][k]
__device__ __half g_ph[(size_t)BATCH * SEQ * SEQ];   // unnormalized exp(score)
__device__ float  g_psum[(size_t)MROWS * 64];        // partial row sums

// GEMM config: CTA 128x128xBK64; 8 warps as 2(M) x 4(N); warp tile 64x32.
// 3-stage cp.async pipeline, 32 KB/stage, 96 KB/CTA -> 2 CTAs per SM.
#define BM 128
#define BN 128
#define BK 64
#define NTH 256
#define STAGES 3
#define A_BUF 16384
#define B_BUF 16384
#define STAGE_BYTES (A_BUF + B_BUF)          // 32768
#define SMEM_TOTAL (STAGES * STAGE_BYTES)    // 98304

// Row = 64 halves = 128 B = 8 x 16B chunks. addr = row*128 + (c ^ (row&7))*16.
__device__ __forceinline__ uint32_t swz(int row, int chunk) {
    return ((uint32_t)row << 7) + ((uint32_t)(chunk ^ (row & 7)) << 4);
}

// Epilogue modes
#define MODE_HALF 0
#define MODE_EXP  1
#define MODE_PV   2
#define MODE_VT   3   // write fp16 transposed into V^T [dim][seq] per batch

// ---------------------------------------------------------------------------
__device__ __forceinline__ uint32_t smem_u32(const void* p) {
    uint32_t a;
    asm("{ .reg .u64 t; cvta.to.shared.u64 t, %1; cvt.u32.u64 %0, t; }"
        : "=r"(a) : "l"(p));
    return a;
}

__device__ __forceinline__ void cp16(uint32_t dst, const void* src) {
    asm volatile("cp.async.cg.shared.global [%0], [%1], 16;"
                 :: "r"(dst), "l"(src));
}
#define CP_COMMIT() asm volatile("cp.async.commit_group;" ::: "memory")
#define CP_WAIT1()  asm volatile("cp.async.wait_group 1;" ::: "memory")

__device__ __forceinline__ void ldsm4(uint32_t r[4], uint32_t addr) {
    asm volatile("ldmatrix.sync.aligned.m8n8.x4.shared.b16 {%0,%1,%2,%3}, [%4];"
                 : "=r"(r[0]), "=r"(r[1]), "=r"(r[2]), "=r"(r[3]) : "r"(addr));
}

__device__ __forceinline__ void mma_f16(float c[4], const uint32_t a[4],
                                        uint32_t b0, uint32_t b1) {
    asm volatile(
        "mma.sync.aligned.m16n8k16.row.col.f32.f16.f16.f32 "
        "{%0,%1,%2,%3}, {%4,%5,%6,%7}, {%8,%9}, {%0,%1,%2,%3};"
        : "+f"(c[0]), "+f"(c[1]), "+f"(c[2]), "+f"(c[3])
        : "r"(a[0]), "r"(a[1]), "r"(a[2]), "r"(a[3]), "r"(b0), "r"(b1));
}

// Split k-stage issue: A half and B half (4 cp16/thread each).
__device__ __forceinline__ void issue_A(const __half* __restrict__ Ag, int lda,
                                        uint32_t sm, int ks, int buf, int tid) {
    const __half* a = Ag + (size_t)ks * BK;
    const uint32_t ab = sm + buf * STAGE_BYTES;
    #pragma unroll
    for (int t = 0; t < 4; t++) {
        int idx = tid + t * NTH;
        cp16(ab + swz(idx >> 3, idx & 7),
             a + (size_t)(idx >> 3) * lda + ((idx & 7) << 3));
    }
}
__device__ __forceinline__ void issue_B(const __half* __restrict__ Bg, int ldb,
                                        uint32_t sm, int ks, int buf, int tid) {
    const __half* b = Bg + (size_t)ks * BK;
    const uint32_t bb = sm + buf * STAGE_BYTES + A_BUF;
    #pragma unroll
    for (int t = 0; t < 4; t++) {
        int idx = tid + t * NTH;
        cp16(bb + swz(idx >> 3, idx & 7),
             b + (size_t)(idx >> 3) * ldb + ((idx & 7) << 3));
    }
}

// ---------------------------------------------------------------------------
// Core: C[128x128] = A[128 x nk*64] @ B^T; fp16 K-major operands in gmem.
// cp.async 3-stage, issues interleaved with MMA stream; 2 CTAs/SM.
// MODE_PV: psum_rd/nw -> per-row 1/sum computed in prologue (order matches
// the old reduce kernel bit-for-bit).
// ---------------------------------------------------------------------------
template <int MODE>
__device__ __forceinline__ void gemm_core(const __half* __restrict__ Ag, int lda,
                                          const __half* __restrict__ Bg, int ldb,
                                          void* __restrict__ Cg, int ldc,
                                          int nk, float scale,
                                          int gr0, int gc0,
                                          float* __restrict__ psum,
                                          const float* __restrict__ psum_rd,
                                          int nw, char* smem) {
    __shared__ float rinv_s[BM];
    const uint32_t sm = smem_u32(smem);
    const int tid = threadIdx.x, lane = tid & 31, warp = tid >> 5;
    const int warpM = warp >> 2, warpN = warp & 3;
    const int l15 = lane & 15, lh = lane >> 4;

    // Fully-masked warp sub-tile on diagonal scores tiles: skip MMA math.
    const bool skip_mma =
        (MODE == MODE_EXP) && (gc0 + warpN * 32 > gr0 + warpM * 64 + 63);

    float c[4][4][4] = {};

    issue_A(Ag, lda, sm, 0, 0, tid);
    issue_B(Bg, ldb, sm, 0, 0, tid);
    CP_COMMIT();
    issue_A(Ag, lda, sm, 1, 1, tid);
    issue_B(Bg, ldb, sm, 1, 1, tid);
    CP_COMMIT();

    // PV: compute per-row 1/sum overlapped with the in-flight loads.
    if (MODE == MODE_PV) {
        for (int r = tid; r < BM; r += NTH) {
            const float* p = psum_rd + (size_t)r * 64;
            float ssum = 0.0f;
            for (int j = 0; j < nw; j++) ssum += p[j];
            rinv_s[r] = 1.0f / ssum;
        }
    }

    for (int i = 0; i < nk; i++) {
        CP_WAIT1();
        __syncthreads();
        const uint32_t abase = sm + (i % STAGES) * STAGE_BYTES;
        const uint32_t bbase = abase + A_BUF;
        const bool pre = (i + 2 < nk);
        const int pbuf = (i + 2) % STAGES;
        #pragma unroll
        for (int s = 0; s < 4; s++) {
            uint32_t afr[4][4], bfr[2][4];
            if (!skip_mma) {
                #pragma unroll
                for (int mt = 0; mt < 4; mt++)
                    ldsm4(afr[mt], abase + swz(warpM * 64 + mt * 16 + l15, 2 * s + lh));
                #pragma unroll
                for (int np = 0; np < 2; np++)
                    ldsm4(bfr[np], bbase + swz(warpN * 32 + np * 16 + l15, 2 * s + lh));
            }
            if (s == 0 && pre) issue_A(Ag, lda, sm, i + 2, pbuf, tid);
            if (s == 1 && pre) issue_B(Bg, ldb, sm, i + 2, pbuf, tid);
            if (!skip_mma) {
                #pragma unroll
                for (int mt = 0; mt < 4; mt++)
                    #pragma unroll
                    for (int np = 0; np < 2; np++) {
                        mma_f16(c[mt][2 * np], afr[mt], bfr[np][0], bfr[np][2]);
                        mma_f16(c[mt][2 * np + 1], afr[mt], bfr[np][1], bfr[np][3]);
                    }
            }
        }
        CP_COMMIT();
    }

    // Epilogue
    #pragma unroll
    for (int mt = 0; mt < 4; mt++) {
        const int rl0 = warpM * 64 + mt * 16 + (lane >> 2);
        float rs0 = 0.0f, rs1 = 0.0f;
        float inv0 = 1.0f, inv1 = 1.0f;
        if (MODE == MODE_PV) {
            inv0 = rinv_s[rl0];
            inv1 = rinv_s[rl0 + 8];
        }
        int vb = 0, vs = 0;
        if (MODE == MODE_VT) {
            int gr = gr0 + rl0;
            vb = gr >> 11;
            vs = gr & (SEQ - 1);
        }
        #pragma unroll
        for (int nt = 0; nt < 4; nt++) {
            const int cl = warpN * 32 + nt * 8 + (lane & 3) * 2;
            float v0 = c[mt][nt][0], v1 = c[mt][nt][1];
            float v2 = c[mt][nt][2], v3 = c[mt][nt][3];
            if (MODE == MODE_HALF) {
                __half* C = reinterpret_cast<__half*>(Cg);
                *reinterpret_cast<__half2*>(&C[(size_t)rl0 * ldc + cl]) =
                    __floats2half2_rn(v0, v1);
                *reinterpret_cast<__half2*>(&C[(size_t)(rl0 + 8) * ldc + cl]) =
                    __floats2half2_rn(v2, v3);
            } else if (MODE == MODE_VT) {
                __half* VT = reinterpret_cast<__half*>(Cg);
                const int gc = gc0 + cl;
                size_t o = ((size_t)vb * DIM + gc) * SEQ + vs;
                VT[o]           = __float2half_rn(v0);
                VT[o + SEQ]     = __float2half_rn(v1);
                VT[o + 8]       = __float2half_rn(v2);
                VT[o + SEQ + 8] = __float2half_rn(v3);
            } else if (MODE == MODE_EXP) {
                const int gc = gc0 + cl;
                const int r0 = gr0 + rl0, r1 = r0 + 8;
                float e0 = (gc     <= r0) ? __expf(v0 * scale) : 0.0f;
                float e1 = (gc + 1 <= r0) ? __expf(v1 * scale) : 0.0f;
                float e2 = (gc     <= r1) ? __expf(v2 * scale) : 0.0f;
                float e3 = (gc + 1 <= r1) ? __expf(v3 * scale) : 0.0f;
                rs0 += e0 + e1;
                rs1 += e2 + e3;
                __half* C = reinterpret_cast<__half*>(Cg);
                *reinterpret_cast<__half2*>(&C[(size_t)rl0 * ldc + cl]) =
                    __floats2half2_rn(e0, e1);
                *reinterpret_cast<__half2*>(&C[(size_t)(rl0 + 8) * ldc + cl]) =
                    __floats2half2_rn(e2, e3);
            } else {
                float* C = reinterpret_cast<float*>(Cg);
                *reinterpret_cast<float2*>(&C[(size_t)rl0 * ldc + cl]) =
                    make_float2(v0 * inv0, v1 * inv0);
                *reinterpret_cast<float2*>(&C[(size_t)(rl0 + 8) * ldc + cl]) =
                    make_float2(v2 * inv1, v3 * inv1);
            }
        }
        if (MODE == MODE_EXP) {
            #pragma unroll
            for (int o = 1; o < 4; o <<= 1) {
                rs0 += __shfl_xor_sync(~0u, rs0, o);
                rs1 += __shfl_xor_sync(~0u, rs1, o);
            }
            if ((lane & 3) == 0) {
                psum[(size_t)rl0 * 64 + warpN] = rs0;
                psum[(size_t)(rl0 + 8) * 64 + warpN] = rs1;
            }
        }
    }
}

// ---------------------------------------------------------------------------
// GEMM kernels (heavy-first by-remap on scores/pv); 2 CTAs/SM.
// ---------------------------------------------------------------------------
__global__ __launch_bounds__(NTH, 2)
void mm_qkv() {
    extern __shared__ char smem[];
    const int which = blockIdx.z;
    const int row0 = blockIdx.y * BM, col0 = blockIdx.x * BN;
    const __half* A = g_xh + (size_t)row0 * DIM;
    const __half* B = g_wth + (size_t)which * DIM * DIM + (size_t)col0 * DIM;
    if (which == 2) {
        gemm_core<MODE_VT>(A, DIM, B, DIM, g_vth, 0, DIM / BK, 1.0f,
                           row0, col0, nullptr, nullptr, 0, smem);
    } else {
        __half* C = ((which == 0) ? g_qh : g_kh) + (size_t)row0 * DIM + col0;
        gemm_core<MODE_HALF>(A, DIM, B, DIM, C, DIM, DIM / BK, 1.0f,
                             0, 0, nullptr, nullptr, 0, smem);
    }
}

__global__ __launch_bounds__(NTH, 2)
void mm_scores(float scale) {
    const int bx = blockIdx.x;
    const int by = (gridDim.y - 1) - blockIdx.y;   // heavy tiles first
    if (bx > by) return;                            // fully-masked key tile
    extern __shared__ char smem[];
    const int b = blockIdx.z;
    const int row0 = by * BM, col0 = bx * BN;
    const __half* A = g_qh + (size_t)b * SEQ * DIM + (size_t)row0 * DIM;
    const __half* B = g_kh + (size_t)b * SEQ * DIM + (size_t)col0 * DIM;
    __half* C = g_ph + (size_t)b * SEQ * SEQ + (size_t)row0 * SEQ + col0;
    float* psum = g_psum + (size_t)(b * SEQ + row0) * 64 + bx * 4;
    gemm_core<MODE_EXP>(A, DIM, B, DIM, C, SEQ, DIM / BK, scale,
                        row0, col0, psum, nullptr, 0, smem);
}

__global__ __launch_bounds__(NTH, 2)
void mm_pv(float* __restrict__ out) {
    extern __shared__ char smem[];
    const int b = blockIdx.z;
    const int by = (gridDim.y - 1) - blockIdx.y;   // heavy tiles first
    const int row0 = by * BM, col0 = blockIdx.x * BN;
    const __half* A = g_ph + (size_t)b * SEQ * SEQ + (size_t)row0 * SEQ;
    const __half* B = g_vth + (size_t)b * DIM * SEQ + (size_t)col0 * SEQ;
    float* C = out + (size_t)b * SEQ * DIM + (size_t)row0 * DIM + col0;
    const float* psum_rd = g_psum + (size_t)(b * SEQ + row0) * 64;
    gemm_core<MODE_PV>(A, SEQ, B, SEQ, C, DIM, 2 * (by + 1), 1.0f,
                       0, 0, nullptr, psum_rd, 4 * (by + 1), smem);
}

// ---------------------------------------------------------------------------
// Prep kernels
// ---------------------------------------------------------------------------
__global__ void round_x(const float* __restrict__ x) {
    size_t i = (size_t)(blockIdx.x * blockDim.x + threadIdx.x) * 4;
    float4 v = *reinterpret_cast<const float4*>(x + i);
    *reinterpret_cast<__half2*>(g_xh + i) = __floats2half2_rn(v.x, v.y);
    *reinterpret_cast<__half2*>(g_xh + i + 2) = __floats2half2_rn(v.z, v.w);
}

__global__ void tr_w(const float* __restrict__ Wq, const float* __restrict__ Wk,
                     const float* __restrict__ Wv) {
    __shared__ float t[32][33];
    const int z = blockIdx.z;
    const float* S = (z == 0) ? Wq : (z == 1) ? Wk : Wv;
    __half* D = g_wth + (size_t)z * DIM * DIM;
    const int x0 = blockIdx.x * 32, y0 = blockIdx.y * 32;
    const int tx = threadIdx.x, ty = threadIdx.y;
    #pragma unroll
    for (int j = 0; j < 32; j += 8)
        t[ty + j][tx] = S[(size_t)(y0 + ty + j) * DIM + x0 + tx];
    __syncthreads();
    #pragma unroll
    for (int j = 0; j < 32; j += 8)
        D[(size_t)(x0 + ty + j) * DIM + y0 + tx] = __float2half_rn(t[tx][ty + j]);
}

// ---------------------------------------------------------------------------
extern "C" void kernel_launch(void* const* d_in, const int* in_sizes, int n_in,
                              void* d_out, int out_size) {
    const float* x  = (const float*)d_in[0];
    const float* Wq = (const float*)d_in[1];
    const float* Wk = (const float*)d_in[2];
    const float* Wv = (const float*)d_in[3];
    float* out = (float*)d_out;

    cudaFuncSetAttribute(mm_qkv, cudaFuncAttributeMaxDynamicSharedMemorySize, SMEM_TOTAL);
    cudaFuncSetAttribute(mm_scores, cudaFuncAttributeMaxDynamicSharedMemorySize, SMEM_TOTAL);
    cudaFuncSetAttribute(mm_pv, cudaFuncAttributeMaxDynamicSharedMemorySize, SMEM_TOTAL);

    round_x<<<(MROWS * DIM) / (4 * 256), 256>>>(x);
    tr_w<<<dim3(32, 32, 3), dim3(32, 8)>>>(Wq, Wk, Wv);
    mm_qkv<<<dim3(DIM / BN, MROWS / BM, 3), NTH, SMEM_TOTAL>>>();
    const float scale = 1.0f / sqrtf((float)DIM);
    mm_scores<<<dim3(SEQ / BN, SEQ / BM, BATCH), NTH, SMEM_TOTAL>>>(scale);
    mm_pv<<<dim3(DIM / BN, SEQ / BM, BATCH), NTH, SMEM_TOTAL>>>(out);
}

// round 16
// speedup vs baseline: 1.0214x; 1.0214x over previous
#include <cuda_runtime.h>
#include <cuda_fp16.h>
#include <math.h>
#include <stdint.h>

#define BATCH 4
#define SEQ   2048
#define DIM   1024
#define MROWS (BATCH * SEQ)

// Scratch (__device__ globals). GEMM inputs in fp16 (rounded at producer).
__device__ __half g_xh[MROWS * DIM];
__device__ __half g_qh[BATCH * SEQ * DIM];
__device__ __half g_kh[BATCH * SEQ * DIM];
__device__ __half g_vth[BATCH * DIM * SEQ];          // V^T [dim][seq]
__device__ __half g_wth[3 * DIM * DIM];              // W^T [n][k]
__device__ __half g_ph[(size_t)BATCH * SEQ * SEQ];   // unnormalized exp(score)
__device__ float  g_psum[(size_t)MROWS * 64];        // partial row sums

// GEMM config: CTA 128x128xBK64; 8 warps as 2(M) x 4(N); warp tile 64x32.
// 3-stage cp.async pipeline, 32 KB/stage, 96 KB/CTA -> 2 CTAs per SM.
#define BM 128
#define BN 128
#define BK 64
#define NTH 256
#define STAGES 3
#define A_BUF 16384
#define B_BUF 16384
#define STAGE_BYTES (A_BUF + B_BUF)          // 32768
#define SMEM_TOTAL (STAGES * STAGE_BYTES)    // 98304

// Row = 64 halves = 128 B = 8 x 16B chunks. addr = row*128 + (c ^ (row&7))*16.
__device__ __forceinline__ uint32_t swz(int row, int chunk) {
    return ((uint32_t)row << 7) + ((uint32_t)(chunk ^ (row & 7)) << 4);
}

// Epilogue modes
#define MODE_HALF 0
#define MODE_EXP  1
#define MODE_PV   2
#define MODE_VT   3   // write fp16 transposed into V^T [dim][seq] per batch

// ---------------------------------------------------------------------------
__device__ __forceinline__ uint32_t smem_u32(const void* p) {
    uint32_t a;
    asm("{ .reg .u64 t; cvta.to.shared.u64 t, %1; cvt.u32.u64 %0, t; }"
        : "=r"(a) : "l"(p));
    return a;
}

__device__ __forceinline__ void cp16(uint32_t dst, const void* src) {
    asm volatile("cp.async.cg.shared.global [%0], [%1], 16;"
                 :: "r"(dst), "l"(src));
}
#define CP_COMMIT() asm volatile("cp.async.commit_group;" ::: "memory")
#define CP_WAIT1()  asm volatile("cp.async.wait_group 1;" ::: "memory")

__device__ __forceinline__ void ldsm4(uint32_t r[4], uint32_t addr) {
    asm volatile("ldmatrix.sync.aligned.m8n8.x4.shared.b16 {%0,%1,%2,%3}, [%4];"
                 : "=r"(r[0]), "=r"(r[1]), "=r"(r[2]), "=r"(r[3]) : "r"(addr));
}

__device__ __forceinline__ void mma_f16(float c[4], const uint32_t a[4],
                                        uint32_t b0, uint32_t b1) {
    asm volatile(
        "mma.sync.aligned.m16n8k16.row.col.f32.f16.f16.f32 "
        "{%0,%1,%2,%3}, {%4,%5,%6,%7}, {%8,%9}, {%0,%1,%2,%3};"
        : "+f"(c[0]), "+f"(c[1]), "+f"(c[2]), "+f"(c[3])
        : "r"(a[0]), "r"(a[1]), "r"(a[2]), "r"(a[3]), "r"(b0), "r"(b1));
}

// Issue one k-stage's cp.async loads (A: 4/thread, B: 4/thread @256 thr).
__device__ __forceinline__ void issue_stage(const __half* __restrict__ Ag, int lda,
                                            const __half* __restrict__ Bg, int ldb,
                                            uint32_t sm, int ks, int buf, int tid) {
    const __half* a = Ag + (size_t)ks * BK;
    const uint32_t ab = sm + buf * STAGE_BYTES;
    #pragma unroll
    for (int t = 0; t < 4; t++) {
        int idx = tid + t * NTH;
        int row = idx >> 3, ch = idx & 7;
        cp16(ab + swz(row, ch), a + (size_t)row * lda + (ch << 3));
    }
    const __half* b = Bg + (size_t)ks * BK;
    const uint32_t bb = ab + A_BUF;
    #pragma unroll
    for (int t = 0; t < 4; t++) {
        int idx = tid + t * NTH;
        int row = idx >> 3, ch = idx & 7;
        cp16(bb + swz(row, ch), b + (size_t)row * ldb + (ch << 3));
    }
}

// ---------------------------------------------------------------------------
// Core: C[128x128] = A[128 x nk*64] @ B^T; fp16 K-major operands in gmem.
// cp.async 3-stage; B-fragment double buffering; 2 CTAs/SM.
// MODE_PV: per-row 1/sum computed in prologue from psum_rd (same summation
// order as the old reduce kernel -> bit-identical), overlapped with loads.
// ---------------------------------------------------------------------------
template <int MODE>
__device__ __forceinline__ void gemm_core(const __half* __restrict__ Ag, int lda,
                                          const __half* __restrict__ Bg, int ldb,
                                          void* __restrict__ Cg, int ldc,
                                          int nk, float scale,
                                          int gr0, int gc0,
                                          float* __restrict__ psum,
                                          const float* __restrict__ psum_rd,
                                          int nw, char* smem) {
    __shared__ float rinv_s[BM];
    const uint32_t sm = smem_u32(smem);
    const int tid = threadIdx.x, lane = tid & 31, warp = tid >> 5;
    const int warpM = warp >> 2, warpN = warp & 3;
    const int l15 = lane & 15, lh = lane >> 4;

    float c[4][4][4] = {};

    issue_stage(Ag, lda, Bg, ldb, sm, 0, 0, tid);
    CP_COMMIT();
    issue_stage(Ag, lda, Bg, ldb, sm, 1, 1, tid);
    CP_COMMIT();

    // PV: per-row 1/sum, overlapped with in-flight cp.async stages.
    if (MODE == MODE_PV) {
        for (int r = tid; r < BM; r += NTH) {
            const float* p = psum_rd + (size_t)r * 64;
            float ssum = 0.0f;
            for (int j = 0; j < nw; j++) ssum += p[j];
            rinv_s[r] = 1.0f / ssum;
        }
    }

    for (int i = 0; i < nk; i++) {
        CP_WAIT1();
        __syncthreads();
        if (i + 2 < nk)
            issue_stage(Ag, lda, Bg, ldb, sm, i + 2, (i + 2) % STAGES, tid);
        CP_COMMIT();
        const uint32_t abase = sm + (i % STAGES) * STAGE_BYTES;
        const uint32_t bbase = abase + A_BUF;
        uint32_t bfr[2][2][4];
        #pragma unroll
        for (int np = 0; np < 2; np++)
            ldsm4(bfr[0][np], bbase + swz(warpN * 32 + np * 16 + l15, lh));
        #pragma unroll
        for (int s = 0; s < 4; s++) {
            const int cur = s & 1;
            if (s < 3) {
                #pragma unroll
                for (int np = 0; np < 2; np++)
                    ldsm4(bfr[cur ^ 1][np],
                          bbase + swz(warpN * 32 + np * 16 + l15, 2 * (s + 1) + lh));
            }
            uint32_t afr[4][4];
            #pragma unroll
            for (int mt = 0; mt < 4; mt++)
                ldsm4(afr[mt], abase + swz(warpM * 64 + mt * 16 + l15, 2 * s + lh));
            #pragma unroll
            for (int mt = 0; mt < 4; mt++)
                #pragma unroll
                for (int np = 0; np < 2; np++) {
                    mma_f16(c[mt][2 * np], afr[mt], bfr[cur][np][0], bfr[cur][np][2]);
                    mma_f16(c[mt][2 * np + 1], afr[mt], bfr[cur][np][1], bfr[cur][np][3]);
                }
        }
    }

    // Epilogue
    #pragma unroll
    for (int mt = 0; mt < 4; mt++) {
        const int rl0 = warpM * 64 + mt * 16 + (lane >> 2);
        float rs0 = 0.0f, rs1 = 0.0f;
        float inv0 = 1.0f, inv1 = 1.0f;
        if (MODE == MODE_PV) {
            inv0 = rinv_s[rl0];
            inv1 = rinv_s[rl0 + 8];
        }
        int vb = 0, vs = 0;
        if (MODE == MODE_VT) {
            int gr = gr0 + rl0;
            vb = gr >> 11;
            vs = gr & (SEQ - 1);
        }
        #pragma unroll
        for (int nt = 0; nt < 4; nt++) {
            const int cl = warpN * 32 + nt * 8 + (lane & 3) * 2;
            float v0 = c[mt][nt][0], v1 = c[mt][nt][1];
            float v2 = c[mt][nt][2], v3 = c[mt][nt][3];
            if (MODE == MODE_HALF) {
                __half* C = reinterpret_cast<__half*>(Cg);
                *reinterpret_cast<__half2*>(&C[(size_t)rl0 * ldc + cl]) =
                    __floats2half2_rn(v0, v1);
                *reinterpret_cast<__half2*>(&C[(size_t)(rl0 + 8) * ldc + cl]) =
                    __floats2half2_rn(v2, v3);
            } else if (MODE == MODE_VT) {
                __half* VT = reinterpret_cast<__half*>(Cg);
                const int gc = gc0 + cl;
                size_t o = ((size_t)vb * DIM + gc) * SEQ + vs;
                VT[o]           = __float2half_rn(v0);
                VT[o + SEQ]     = __float2half_rn(v1);
                VT[o + 8]       = __float2half_rn(v2);
                VT[o + SEQ + 8] = __float2half_rn(v3);
            } else if (MODE == MODE_EXP) {
                const int gc = gc0 + cl;
                const int r0 = gr0 + rl0, r1 = r0 + 8;
                float e0 = (gc     <= r0) ? __expf(v0 * scale) : 0.0f;
                float e1 = (gc + 1 <= r0) ? __expf(v1 * scale) : 0.0f;
                float e2 = (gc     <= r1) ? __expf(v2 * scale) : 0.0f;
                float e3 = (gc + 1 <= r1) ? __expf(v3 * scale) : 0.0f;
                rs0 += e0 + e1;
                rs1 += e2 + e3;
                __half* C = reinterpret_cast<__half*>(Cg);
                *reinterpret_cast<__half2*>(&C[(size_t)rl0 * ldc + cl]) =
                    __floats2half2_rn(e0, e1);
                *reinterpret_cast<__half2*>(&C[(size_t)(rl0 + 8) * ldc + cl]) =
                    __floats2half2_rn(e2, e3);
            } else {
                float* C = reinterpret_cast<float*>(Cg);
                *reinterpret_cast<float2*>(&C[(size_t)rl0 * ldc + cl]) =
                    make_float2(v0 * inv0, v1 * inv0);
                *reinterpret_cast<float2*>(&C[(size_t)(rl0 + 8) * ldc + cl]) =
                    make_float2(v2 * inv1, v3 * inv1);
            }
        }
        if (MODE == MODE_EXP) {
            #pragma unroll
            for (int o = 1; o < 4; o <<= 1) {
                rs0 += __shfl_xor_sync(~0u, rs0, o);
                rs1 += __shfl_xor_sync(~0u, rs1, o);
            }
            if ((lane & 3) == 0) {
                psum[(size_t)rl0 * 64 + warpN] = rs0;
                psum[(size_t)(rl0 + 8) * 64 + warpN] = rs1;
            }
        }
    }
}

// ---------------------------------------------------------------------------
// GEMM kernels (heavy-first by-remap on scores/pv); 2 CTAs/SM.
// ---------------------------------------------------------------------------
__global__ __launch_bounds__(NTH, 2)
void mm_qkv() {
    extern __shared__ char smem[];
    const int which = blockIdx.z;
    const int row0 = blockIdx.y * BM, col0 = blockIdx.x * BN;
    const __half* A = g_xh + (size_t)row0 * DIM;
    const __half* B = g_wth + (size_t)which * DIM * DIM + (size_t)col0 * DIM;
    if (which == 2) {
        gemm_core<MODE_VT>(A, DIM, B, DIM, g_vth, 0, DIM / BK, 1.0f,
                           row0, col0, nullptr, nullptr, 0, smem);
    } else {
        __half* C = ((which == 0) ? g_qh : g_kh) + (size_t)row0 * DIM + col0;
        gemm_core<MODE_HALF>(A, DIM, B, DIM, C, DIM, DIM / BK, 1.0f,
                             0, 0, nullptr, nullptr, 0, smem);
    }
}

__global__ __launch_bounds__(NTH, 2)
void mm_scores(float scale) {
    const int bx = blockIdx.x;
    const int by = (gridDim.y - 1) - blockIdx.y;   // heavy tiles first
    if (bx > by) return;                            // fully-masked key tile
    extern __shared__ char smem[];
    const int b = blockIdx.z;
    const int row0 = by * BM, col0 = bx * BN;
    const __half* A = g_qh + (size_t)b * SEQ * DIM + (size_t)row0 * DIM;
    const __half* B = g_kh + (size_t)b * SEQ * DIM + (size_t)col0 * DIM;
    __half* C = g_ph + (size_t)b * SEQ * SEQ + (size_t)row0 * SEQ + col0;
    float* psum = g_psum + (size_t)(b * SEQ + row0) * 64 + bx * 4;
    gemm_core<MODE_EXP>(A, DIM, B, DIM, C, SEQ, DIM / BK, scale,
                        row0, col0, psum, nullptr, 0, smem);
}

__global__ __launch_bounds__(NTH, 2)
void mm_pv(float* __restrict__ out) {
    extern __shared__ char smem[];
    const int b = blockIdx.z;
    const int by = (gridDim.y - 1) - blockIdx.y;   // heavy tiles first
    const int row0 = by * BM, col0 = blockIdx.x * BN;
    const __half* A = g_ph + (size_t)b * SEQ * SEQ + (size_t)row0 * SEQ;
    const __half* B = g_vth + (size_t)b * DIM * SEQ + (size_t)col0 * SEQ;
    float* C = out + (size_t)b * SEQ * DIM + (size_t)row0 * DIM + col0;
    const float* psum_rd = g_psum + (size_t)(b * SEQ + row0) * 64;
    gemm_core<MODE_PV>(A, SEQ, B, SEQ, C, DIM, 2 * (by + 1), 1.0f,
                       0, 0, nullptr, psum_rd, 4 * (by + 1), smem);
}

// ---------------------------------------------------------------------------
// Prep kernels
// ---------------------------------------------------------------------------
__global__ void round_x(const float* __restrict__ x) {
    size_t i = (size_t)(blockIdx.x * blockDim.x + threadIdx.x) * 4;
    float4 v = *reinterpret_cast<const float4*>(x + i);
    *reinterpret_cast<__half2*>(g_xh + i) = __floats2half2_rn(v.x, v.y);
    *reinterpret_cast<__half2*>(g_xh + i + 2) = __floats2half2_rn(v.z, v.w);
}

__global__ void tr_w(const float* __restrict__ Wq, const float* __restrict__ Wk,
                     const float* __restrict__ Wv) {
    __shared__ float t[32][33];
    const int z = blockIdx.z;
    const float* S = (z == 0) ? Wq : (z == 1) ? Wk : Wv;
    __half* D = g_wth + (size_t)z * DIM * DIM;
    const int x0 = blockIdx.x * 32, y0 = blockIdx.y * 32;
    const int tx = threadIdx.x, ty = threadIdx.y;
    #pragma unroll
    for (int j = 0; j < 32; j += 8)
        t[ty + j][tx] = S[(size_t)(y0 + ty + j) * DIM + x0 + tx];
    __syncthreads();
    #pragma unroll
    for (int j = 0; j < 32; j += 8)
        D[(size_t)(x0 + ty + j) * DIM + y0 + tx] = __float2half_rn(t[tx][ty + j]);
}

// ---------------------------------------------------------------------------
extern "C" void kernel_launch(void* const* d_in, const int* in_sizes, int n_in,
                              void* d_out, int out_size) {
    const float* x  = (const float*)d_in[0];
    const float* Wq = (const float*)d_in[1];
    const float* Wk = (const float*)d_in[2];
    const float* Wv = (const float*)d_in[3];
    float* out = (float*)d_out;

    cudaFuncSetAttribute(mm_qkv, cudaFuncAttributeMaxDynamicSharedMemorySize, SMEM_TOTAL);
    cudaFuncSetAttribute(mm_scores, cudaFuncAttributeMaxDynamicSharedMemorySize, SMEM_TOTAL);
    cudaFuncSetAttribute(mm_pv, cudaFuncAttributeMaxDynamicSharedMemorySize, SMEM_TOTAL);

    round_x<<<(MROWS * DIM) / (4 * 256), 256>>>(x);
    tr_w<<<dim3(32, 32, 3), dim3(32, 8)>>>(Wq, Wk, Wv);
    mm_qkv<<<dim3(DIM / BN, MROWS / BM, 3), NTH, SMEM_TOTAL>>>();
    const float scale = 1.0f / sqrtf((float)DIM);
    mm_scores<<<dim3(SEQ / BN, SEQ / BM, BATCH), NTH, SMEM_TOTAL>>>(scale);
    mm_pv<<<dim3(DIM / BN, SEQ / BM, BATCH), NTH, SMEM_TOTAL>>>(out);
}

// round 17
// speedup vs baseline: 1.0328x; 1.0112x over previous
#include <cuda_runtime.h>
#include <cuda_fp16.h>
#include <math.h>
#include <stdint.h>

#define BATCH 4
#define SEQ   2048
#define DIM   1024
#define MROWS (BATCH * SEQ)

// Scratch (__device__ globals). GEMM inputs in fp16 (rounded at producer).
__device__ __half g_xh[MROWS * DIM];
__device__ __half g_qh[BATCH * SEQ * DIM];
__device__ __half g_kh[BATCH * SEQ * DIM];
__device__ __half g_vth[BATCH * DIM * SEQ];          // V^T [dim][seq]
__device__ __half g_wth[3 * DIM * DIM];              // W^T [n][k]
__device__ __half g_ph[(size_t)BATCH * SEQ * SEQ];   // unnormalized exp(score)
__device__ float  g_psum[(size_t)MROWS * 64];        // partial row sums

// GEMM config: CTA 128x128xBK64; 8 warps as 2(M) x 4(N); warp tile 64x32.
// 3-stage cp.async pipeline, 32 KB/stage, 96 KB/CTA -> 2 CTAs per SM.
#define BM 128
#define BN 128
#define BK 64
#define NTH 256
#define STAGES 3
#define A_BUF 16384
#define B_BUF 16384
#define STAGE_BYTES (A_BUF + B_BUF)          // 32768
#define SMEM_TOTAL (STAGES * STAGE_BYTES)    // 98304

// Row = 64 halves = 128 B = 8 x 16B chunks. addr = row*128 + (c ^ (row&7))*16.
__device__ __forceinline__ uint32_t swz(int row, int chunk) {
    return ((uint32_t)row << 7) + ((uint32_t)(chunk ^ (row & 7)) << 4);
}

// Epilogue modes
#define MODE_HALF 0
#define MODE_EXP  1
#define MODE_PV   2
#define MODE_VT   3   // write fp16 transposed into V^T [dim][seq] per batch

// ---------------------------------------------------------------------------
__device__ __forceinline__ uint32_t smem_u32(const void* p) {
    uint32_t a;
    asm("{ .reg .u64 t; cvta.to.shared.u64 t, %1; cvt.u32.u64 %0, t; }"
        : "=r"(a) : "l"(p));
    return a;
}

__device__ __forceinline__ void cp16(uint32_t dst, const void* src) {
    asm volatile("cp.async.cg.shared.global [%0], [%1], 16;"
                 :: "r"(dst), "l"(src));
}
#define CP_COMMIT() asm volatile("cp.async.commit_group;" ::: "memory")
#define CP_WAIT1()  asm volatile("cp.async.wait_group 1;" ::: "memory")

__device__ __forceinline__ void ldsm4(uint32_t r[4], uint32_t addr) {
    asm volatile("ldmatrix.sync.aligned.m8n8.x4.shared.b16 {%0,%1,%2,%3}, [%4];"
                 : "=r"(r[0]), "=r"(r[1]), "=r"(r[2]), "=r"(r[3]) : "r"(addr));
}

__device__ __forceinline__ void mma_f16(float c[4], const uint32_t a[4],
                                        uint32_t b0, uint32_t b1) {
    asm volatile(
        "mma.sync.aligned.m16n8k16.row.col.f32.f16.f16.f32 "
        "{%0,%1,%2,%3}, {%4,%5,%6,%7}, {%8,%9}, {%0,%1,%2,%3};"
        : "+f"(c[0]), "+f"(c[1]), "+f"(c[2]), "+f"(c[3])
        : "r"(a[0]), "r"(a[1]), "r"(a[2]), "r"(a[3]), "r"(b0), "r"(b1));
}

// Issue one k-stage's cp.async loads (A: 4/thread, B: 4/thread @256 thr).
__device__ __forceinline__ void issue_stage(const __half* __restrict__ Ag, int lda,
                                            const __half* __restrict__ Bg, int ldb,
                                            uint32_t sm, int ks, int buf, int tid) {
    const __half* a = Ag + (size_t)ks * BK;
    const uint32_t ab = sm + buf * STAGE_BYTES;
    #pragma unroll
    for (int t = 0; t < 4; t++) {
        int idx = tid + t * NTH;
        int row = idx >> 3, ch = idx & 7;
        cp16(ab + swz(row, ch), a + (size_t)row * lda + (ch << 3));
    }
    const __half* b = Bg + (size_t)ks * BK;
    const uint32_t bb = ab + A_BUF;
    #pragma unroll
    for (int t = 0; t < 4; t++) {
        int idx = tid + t * NTH;
        int row = idx >> 3, ch = idx & 7;
        cp16(bb + swz(row, ch), b + (size_t)row * ldb + (ch << 3));
    }
}

// ---------------------------------------------------------------------------
// Core: C[128x128] = A[128 x nk*64] @ B^T; fp16 K-major operands in gmem.
// cp.async 3-stage; hoisted ldmatrix addressing (swz is per-thread invariant:
// swz(row+16k, c) = swz(row, c) + 2048k); 2 CTAs/SM.
// MODE_PV: per-row 1/sum computed in prologue from psum_rd (same summation
// order as the old reduce kernel -> bit-identical), overlapped with loads.
// ---------------------------------------------------------------------------
template <int MODE>
__device__ __forceinline__ void gemm_core(const __half* __restrict__ Ag, int lda,
                                          const __half* __restrict__ Bg, int ldb,
                                          void* __restrict__ Cg, int ldc,
                                          int nk, float scale,
                                          int gr0, int gc0,
                                          float* __restrict__ psum,
                                          const float* __restrict__ psum_rd,
                                          int nw, char* smem) {
    __shared__ float rinv_s[BM];
    const uint32_t sm = smem_u32(smem);
    const int tid = threadIdx.x, lane = tid & 31, warp = tid >> 5;
    const int warpM = warp >> 2, warpN = warp & 3;
    const int l15 = lane & 15, lh = lane >> 4;

    // Hoisted per-thread ldmatrix offsets (loop-invariant).
    uint32_t aoff[4], boff[4];
    #pragma unroll
    for (int s = 0; s < 4; s++) {
        aoff[s] = swz(warpM * 64 + l15, 2 * s + lh);
        boff[s] = swz(warpN * 32 + l15, 2 * s + lh) + A_BUF;
    }

    float c[4][4][4] = {};

    issue_stage(Ag, lda, Bg, ldb, sm, 0, 0, tid);
    CP_COMMIT();
    issue_stage(Ag, lda, Bg, ldb, sm, 1, 1, tid);
    CP_COMMIT();

    // PV: per-row 1/sum, overlapped with in-flight cp.async stages.
    if (MODE == MODE_PV) {
        for (int r = tid; r < BM; r += NTH) {
            const float* p = psum_rd + (size_t)r * 64;
            float ssum = 0.0f;
            for (int j = 0; j < nw; j++) ssum += p[j];
            rinv_s[r] = 1.0f / ssum;
        }
    }

    for (int i = 0; i < nk; i++) {
        CP_WAIT1();
        __syncthreads();
        if (i + 2 < nk)
            issue_stage(Ag, lda, Bg, ldb, sm, i + 2, (i + 2) % STAGES, tid);
        CP_COMMIT();
        const uint32_t base = sm + (i % STAGES) * STAGE_BYTES;
        #pragma unroll
        for (int s = 0; s < 4; s++) {
            const uint32_t ab = base + aoff[s];
            const uint32_t bb = base + boff[s];
            uint32_t afr[4][4], bfr[2][4];
            #pragma unroll
            for (int mt = 0; mt < 4; mt++)
                ldsm4(afr[mt], ab + mt * 2048);
            #pragma unroll
            for (int np = 0; np < 2; np++)
                ldsm4(bfr[np], bb + np * 2048);
            #pragma unroll
            for (int mt = 0; mt < 4; mt++)
                #pragma unroll
                for (int np = 0; np < 2; np++) {
                    mma_f16(c[mt][2 * np], afr[mt], bfr[np][0], bfr[np][2]);
                    mma_f16(c[mt][2 * np + 1], afr[mt], bfr[np][1], bfr[np][3]);
                }
        }
    }

    // Epilogue
    #pragma unroll
    for (int mt = 0; mt < 4; mt++) {
        const int rl0 = warpM * 64 + mt * 16 + (lane >> 2);
        float rs0 = 0.0f, rs1 = 0.0f;
        float inv0 = 1.0f, inv1 = 1.0f;
        if (MODE == MODE_PV) {
            inv0 = rinv_s[rl0];
            inv1 = rinv_s[rl0 + 8];
        }
        int vb = 0, vs = 0;
        if (MODE == MODE_VT) {
            int gr = gr0 + rl0;
            vb = gr >> 11;
            vs = gr & (SEQ - 1);
        }
        #pragma unroll
        for (int nt = 0; nt < 4; nt++) {
            const int cl = warpN * 32 + nt * 8 + (lane & 3) * 2;
            float v0 = c[mt][nt][0], v1 = c[mt][nt][1];
            float v2 = c[mt][nt][2], v3 = c[mt][nt][3];
            if (MODE == MODE_HALF) {
                __half* C = reinterpret_cast<__half*>(Cg);
                *reinterpret_cast<__half2*>(&C[(size_t)rl0 * ldc + cl]) =
                    __floats2half2_rn(v0, v1);
                *reinterpret_cast<__half2*>(&C[(size_t)(rl0 + 8) * ldc + cl]) =
                    __floats2half2_rn(v2, v3);
            } else if (MODE == MODE_VT) {
                __half* VT = reinterpret_cast<__half*>(Cg);
                const int gc = gc0 + cl;
                size_t o = ((size_t)vb * DIM + gc) * SEQ + vs;
                VT[o]           = __float2half_rn(v0);
                VT[o + SEQ]     = __float2half_rn(v1);
                VT[o + 8]       = __float2half_rn(v2);
                VT[o + SEQ + 8] = __float2half_rn(v3);
            } else if (MODE == MODE_EXP) {
                const int gc = gc0 + cl;
                const int r0 = gr0 + rl0, r1 = r0 + 8;
                float e0 = (gc     <= r0) ? __expf(v0 * scale) : 0.0f;
                float e1 = (gc + 1 <= r0) ? __expf(v1 * scale) : 0.0f;
                float e2 = (gc     <= r1) ? __expf(v2 * scale) : 0.0f;
                float e3 = (gc + 1 <= r1) ? __expf(v3 * scale) : 0.0f;
                rs0 += e0 + e1;
                rs1 += e2 + e3;
                __half* C = reinterpret_cast<__half*>(Cg);
                *reinterpret_cast<__half2*>(&C[(size_t)rl0 * ldc + cl]) =
                    __floats2half2_rn(e0, e1);
                *reinterpret_cast<__half2*>(&C[(size_t)(rl0 + 8) * ldc + cl]) =
                    __floats2half2_rn(e2, e3);
            } else {
                float* C = reinterpret_cast<float*>(Cg);
                *reinterpret_cast<float2*>(&C[(size_t)rl0 * ldc + cl]) =
                    make_float2(v0 * inv0, v1 * inv0);
                *reinterpret_cast<float2*>(&C[(size_t)(rl0 + 8) * ldc + cl]) =
                    make_float2(v2 * inv1, v3 * inv1);
            }
        }
        if (MODE == MODE_EXP) {
            #pragma unroll
            for (int o = 1; o < 4; o <<= 1) {
                rs0 += __shfl_xor_sync(~0u, rs0, o);
                rs1 += __shfl_xor_sync(~0u, rs1, o);
            }
            if ((lane & 3) == 0) {
                psum[(size_t)rl0 * 64 + warpN] = rs0;
                psum[(size_t)(rl0 + 8) * 64 + warpN] = rs1;
            }
        }
    }
}

// ---------------------------------------------------------------------------
// GEMM kernels (heavy-first by-remap on scores/pv); 2 CTAs/SM.
// ---------------------------------------------------------------------------
__global__ __launch_bounds__(NTH, 2)
void mm_qkv() {
    extern __shared__ char smem[];
    const int which = blockIdx.z;
    const int row0 = blockIdx.y * BM, col0 = blockIdx.x * BN;
    const __half* A = g_xh + (size_t)row0 * DIM;
    const __half* B = g_wth + (size_t)which * DIM * DIM + (size_t)col0 * DIM;
    if (which == 2) {
        gemm_core<MODE_VT>(A, DIM, B, DIM, g_vth, 0, DIM / BK, 1.0f,
                           row0, col0, nullptr, nullptr, 0, smem);
    } else {
        __half* C = ((which == 0) ? g_qh : g_kh) + (size_t)row0 * DIM + col0;
        gemm_core<MODE_HALF>(A, DIM, B, DIM, C, DIM, DIM / BK, 1.0f,
                             0, 0, nullptr, nullptr, 0, smem);
    }
}

__global__ __launch_bounds__(NTH, 2)
void mm_scores(float scale) {
    const int bx = blockIdx.x;
    const int by = (gridDim.y - 1) - blockIdx.y;   // heavy tiles first
    if (bx > by) return;                            // fully-masked key tile
    extern __shared__ char smem[];
    const int b = blockIdx.z;
    const int row0 = by * BM, col0 = bx * BN;
    const __half* A = g_qh + (size_t)b * SEQ * DIM + (size_t)row0 * DIM;
    const __half* B = g_kh + (size_t)b * SEQ * DIM + (size_t)col0 * DIM;
    __half* C = g_ph + (size_t)b * SEQ * SEQ + (size_t)row0 * SEQ + col0;
    float* psum = g_psum + (size_t)(b * SEQ + row0) * 64 + bx * 4;
    gemm_core<MODE_EXP>(A, DIM, B, DIM, C, SEQ, DIM / BK, scale,
                        row0, col0, psum, nullptr, 0, smem);
}

__global__ __launch_bounds__(NTH, 2)
void mm_pv(float* __restrict__ out) {
    extern __shared__ char smem[];
    const int b = blockIdx.z;
    const int by = (gridDim.y - 1) - blockIdx.y;   // heavy tiles first
    const int row0 = by * BM, col0 = blockIdx.x * BN;
    const __half* A = g_ph + (size_t)b * SEQ * SEQ + (size_t)row0 * SEQ;
    const __half* B = g_vth + (size_t)b * DIM * SEQ + (size_t)col0 * SEQ;
    float* C = out + (size_t)b * SEQ * DIM + (size_t)row0 * DIM + col0;
    const float* psum_rd = g_psum + (size_t)(b * SEQ + row0) * 64;
    gemm_core<MODE_PV>(A, SEQ, B, SEQ, C, DIM, 2 * (by + 1), 1.0f,
                       0, 0, nullptr, psum_rd, 4 * (by + 1), smem);
}

// ---------------------------------------------------------------------------
// Prep kernels
// ---------------------------------------------------------------------------
__global__ void round_x(const float* __restrict__ x) {
    size_t i = (size_t)(blockIdx.x * blockDim.x + threadIdx.x) * 4;
    float4 v = *reinterpret_cast<const float4*>(x + i);
    *reinterpret_cast<__half2*>(g_xh + i) = __floats2half2_rn(v.x, v.y);
    *reinterpret_cast<__half2*>(g_xh + i + 2) = __floats2half2_rn(v.z, v.w);
}

__global__ void tr_w(const float* __restrict__ Wq, const float* __restrict__ Wk,
                     const float* __restrict__ Wv) {
    __shared__ float t[32][33];
    const int z = blockIdx.z;
    const float* S = (z == 0) ? Wq : (z == 1) ? Wk : Wv;
    __half* D = g_wth + (size_t)z * DIM * DIM;
    const int x0 = blockIdx.x * 32, y0 = blockIdx.y * 32;
    const int tx = threadIdx.x, ty = threadIdx.y;
    #pragma unroll
    for (int j = 0; j < 32; j += 8)
        t[ty + j][tx] = S[(size_t)(y0 + ty + j) * DIM + x0 + tx];
    __syncthreads();
    #pragma unroll
    for (int j = 0; j < 32; j += 8)
        D[(size_t)(x0 + ty + j) * DIM + y0 + tx] = __float2half_rn(t[tx][ty + j]);
}

// ---------------------------------------------------------------------------
extern "C" void kernel_launch(void* const* d_in, const int* in_sizes, int n_in,
                              void* d_out, int out_size) {
    const float* x  = (const float*)d_in[0];
    const float* Wq = (const float*)d_in[1];
    const float* Wk = (const float*)d_in[2];
    const float* Wv = (const float*)d_in[3];
    float* out = (float*)d_out;

    cudaFuncSetAttribute(mm_qkv, cudaFuncAttributeMaxDynamicSharedMemorySize, SMEM_TOTAL);
    cudaFuncSetAttribute(mm_scores, cudaFuncAttributeMaxDynamicSharedMemorySize, SMEM_TOTAL);
    cudaFuncSetAttribute(mm_pv, cudaFuncAttributeMaxDynamicSharedMemorySize, SMEM_TOTAL);

    round_x<<<(MROWS * DIM) / (4 * 256), 256>>>(x);
    tr_w<<<dim3(32, 32, 3), dim3(32, 8)>>>(Wq, Wk, Wv);
    mm_qkv<<<dim3(DIM / BN, MROWS / BM, 3), NTH, SMEM_TOTAL>>>();
    const float scale = 1.0f / sqrtf((float)DIM);
    mm_scores<<<dim3(SEQ / BN, SEQ / BM, BATCH), NTH, SMEM_TOTAL>>>(scale);
    mm_pv<<<dim3(DIM / BN, SEQ / BM, BATCH), NTH, SMEM_TOTAL>>>(out);
}